// round 1
// baseline (speedup 1.0000x reference)
#include <cuda_runtime.h>
#include <cuda_bf16.h>

// Problem constants
#define Bb 2
#define Cc 256
#define Nn 4096
#define Rr 8
#define Gg 4

#define BM 256   // C tile (full)
#define BN 128   // m tile
#define BK 16    // n (contraction) tile

// ---------------- scratch (device globals; no allocation allowed) -------------
// indexed [dir][batch]
__device__ float g_q[2][Bb][Rr * Nn];
__device__ float g_k[2][Bb][Rr * Nn];
__device__ float g_v[2][Bb][Cc * Nn];
__device__ float g_mx[2][Bb][Nn];
__device__ float g_rz[2][Bb][Nn];
__device__ float g_pmx[2][Bb][4][Nn];
__device__ float g_psum[2][Bb][4][Nn];

// ---------------- f32x2 helpers (Blackwell packed fp32 FMA) -------------------
__device__ __forceinline__ unsigned long long pk2(float lo, float hi) {
    unsigned long long r;
    asm("mov.b64 %0, {%1, %2};" : "=l"(r) : "f"(lo), "f"(hi));
    return r;
}
__device__ __forceinline__ unsigned long long ffma2(unsigned long long a,
                                                    unsigned long long b,
                                                    unsigned long long c) {
    unsigned long long d;
    asm("fma.rn.f32x2 %0, %1, %2, %3;" : "=l"(d) : "l"(a), "l"(b), "l"(c));
    return d;
}
__device__ __forceinline__ float lo32(unsigned long long v) {
    return __uint_as_float((unsigned)(v & 0xffffffffull));
}
__device__ __forceinline__ float hi32(unsigned long long v) {
    return __uint_as_float((unsigned)(v >> 32));
}

// ---------------- projections: two R=8 1x1 convs per field -------------------
// field 0: x=fL -> outA=g_q[0] (w=qL), outB=g_k[1] (w=kL)
// field 1: x=fU -> outA=g_k[0] (w=kU), outB=g_q[1] (w=qU)
__global__ void proj2_kernel(const float* __restrict__ x,
                             const float* __restrict__ wA, const float* __restrict__ bA,
                             const float* __restrict__ wB, const float* __restrict__ bB,
                             int field) {
    __shared__ float ws[2 * Rr * Cc];
    const int tid = threadIdx.x;          // 64 threads
    const int b = blockIdx.y;
    const int n = blockIdx.x * 64 + tid;
    for (int i = tid; i < Rr * Cc; i += 64) {
        ws[i] = wA[i];
        ws[Rr * Cc + i] = wB[i];
    }
    __syncthreads();
    float acc[16];
#pragma unroll
    for (int r = 0; r < Rr; r++) { acc[r] = bA[r]; acc[8 + r] = bB[r]; }
    const float* xb = x + (size_t)b * Cc * Nn + n;
    for (int c = 0; c < Cc; c++) {
        float xv = xb[(size_t)c * Nn];
#pragma unroll
        for (int r = 0; r < Rr; r++) {
            acc[r]     = fmaf(ws[r * Cc + c], xv, acc[r]);
            acc[8 + r] = fmaf(ws[Rr * Cc + r * Cc + c], xv, acc[8 + r]);
        }
    }
    float* outA = (field == 0) ? g_q[0][b] : g_k[0][b];
    float* outB = (field == 0) ? g_k[1][b] : g_q[1][b];
#pragma unroll
    for (int r = 0; r < Rr; r++) {
        outA[r * Nn + n] = acc[r];
        outB[r * Nn + n] = acc[8 + r];
    }
}

// ---------------- grouped 1x1 conv (V projections) ----------------------------
// dir 0: v = vU(xU), dir 1: v = vL(xL)
__global__ void gconv_kernel(const float* __restrict__ fL, const float* __restrict__ fU,
                             const float* __restrict__ wU, const float* __restrict__ bU,
                             const float* __restrict__ wL, const float* __restrict__ bL) {
    const int bd = blockIdx.z;
    const int d = bd & 1;
    const int b = bd >> 1;
    const float* x    = (d == 0) ? fU : fL;
    const float* w    = (d == 0) ? wU : wL;
    const float* bias = (d == 0) ? bU : bL;
    const int g = blockIdx.y;
    const int tid = threadIdx.x;          // 128 threads
    const int n = blockIdx.x * 128 + tid;

    __shared__ float ws[64 * 64];
    for (int i = tid; i < 64 * 64; i += 128) ws[i] = w[g * 4096 + i];
    __syncthreads();

    float acc[64];
#pragma unroll
    for (int co = 0; co < 64; co++) acc[co] = bias[g * 64 + co];

    const float* xb = x + (size_t)b * Cc * Nn + (size_t)(g * 64) * Nn + n;
    for (int ci = 0; ci < 64; ci++) {
        float xv = xb[(size_t)ci * Nn];
#pragma unroll
        for (int co = 0; co < 64; co++)
            acc[co] = fmaf(ws[co * 64 + ci], xv, acc[co]);
    }
    float* vout = g_v[d][b];
#pragma unroll
    for (int co = 0; co < 64; co++)
        vout[(size_t)(g * 64 + co) * Nn + n] = acc[co];
}

// ---------------- softmax row stats: partial max + sumexp per m-chunk ---------
__global__ void stats_kernel() {
    const int bd = blockIdx.z;
    const int d = bd & 1;
    const int b = bd >> 1;
    const int mc = blockIdx.y;            // m chunk of 1024
    const int tid = threadIdx.x;          // 256 threads
    const int n = blockIdx.x * 256 + tid;

    __shared__ float ks[Rr][1024];        // 32 KB
    const float* kp = g_k[d][b];
    const float* qp = g_q[d][b];
    for (int i = tid; i < Rr * 1024; i += 256) {
        int r = i >> 10, mm = i & 1023;
        ks[r][mm] = kp[r * Nn + mc * 1024 + mm];
    }
    __syncthreads();

    float qr[Rr];
#pragma unroll
    for (int r = 0; r < Rr; r++) qr[r] = qp[r * Nn + n];

    float mxl = -3.0e38f;
    for (int m4 = 0; m4 < 256; m4++) {
        float s0 = 0.f, s1 = 0.f, s2 = 0.f, s3 = 0.f;
#pragma unroll
        for (int r = 0; r < Rr; r++) {
            float4 kv = *(const float4*)&ks[r][m4 * 4];
            s0 = fmaf(qr[r], kv.x, s0);
            s1 = fmaf(qr[r], kv.y, s1);
            s2 = fmaf(qr[r], kv.z, s2);
            s3 = fmaf(qr[r], kv.w, s3);
        }
        mxl = fmaxf(mxl, fmaxf(fmaxf(s0, s1), fmaxf(s2, s3)));
    }
    float sum = 0.f;
    for (int m4 = 0; m4 < 256; m4++) {
        float s0 = 0.f, s1 = 0.f, s2 = 0.f, s3 = 0.f;
#pragma unroll
        for (int r = 0; r < Rr; r++) {
            float4 kv = *(const float4*)&ks[r][m4 * 4];
            s0 = fmaf(qr[r], kv.x, s0);
            s1 = fmaf(qr[r], kv.y, s1);
            s2 = fmaf(qr[r], kv.z, s2);
            s3 = fmaf(qr[r], kv.w, s3);
        }
        sum += __expf(s0 - mxl) + __expf(s1 - mxl) + __expf(s2 - mxl) + __expf(s3 - mxl);
    }
    g_pmx[d][b][mc][n] = mxl;
    g_psum[d][b][mc][n] = sum;
}

__global__ void combine_kernel() {
    const int bd = blockIdx.y;
    const int d = bd & 1;
    const int b = bd >> 1;
    const int n = blockIdx.x * 256 + threadIdx.x;
    float m0 = g_pmx[d][b][0][n], m1 = g_pmx[d][b][1][n];
    float m2 = g_pmx[d][b][2][n], m3 = g_pmx[d][b][3][n];
    float gm = fmaxf(fmaxf(m0, m1), fmaxf(m2, m3));
    float Z = g_psum[d][b][0][n] * __expf(m0 - gm)
            + g_psum[d][b][1][n] * __expf(m1 - gm)
            + g_psum[d][b][2][n] * __expf(m2 - gm)
            + g_psum[d][b][3][n] * __expf(m3 - gm);
    g_mx[d][b][n] = gm;
    g_rz[d][b][n] = 1.0f / Z;
}

// ---------------- fused GEMM: out = f + beta * (V*rz) @ exp(Q^T K - mx) -------
__global__ void __launch_bounds__(256, 1)
gemm_kernel(const float* __restrict__ fL, const float* __restrict__ fU,
            const float* __restrict__ beta_p, float* __restrict__ outb) {
    const int bd = blockIdx.y;
    const int d = bd & 1;
    const int b = bd >> 1;
    const float* qp  = g_q[d][b];
    const float* kp  = g_k[d][b];
    const float* vp  = g_v[d][b];
    const float* mxp = g_mx[d][b];
    const float* rzp = g_rz[d][b];
    const float* f = ((d == 0) ? fL : fU) + (size_t)b * Cc * Nn;
    float* outp = outb + (size_t)d * Bb * Cc * Nn + (size_t)b * Cc * Nn;
    const int m0 = blockIdx.x * BN;

    __shared__ float As[Cc][20];          // V*rz tile, [c][kk], padded stride
    __shared__ float Es[BK][BN];          // exp tile
    __shared__ float kt[Rr][BN];          // k vectors for this m-tile
    __shared__ float qs[Rr][BK];
    __shared__ float mxs[BK];

    const int tid = threadIdx.x;
    const int tx = tid & 15, ty = tid >> 4;

    for (int i = tid; i < Rr * BN; i += 256) {
        int r = i >> 7, mm = i & 127;
        kt[r][mm] = kp[r * Nn + m0 + mm];
    }

    unsigned long long acc[8][8];
#pragma unroll
    for (int i = 0; i < 8; i++)
#pragma unroll
        for (int j = 0; j < 8; j++) acc[i][j] = 0ull;

    const int c0 = tid >> 2, kq = tid & 3;

    for (int n0 = 0; n0 < Nn; n0 += BK) {
        __syncthreads();
        // stage A tile (V * rz), transposing to [c][kk]
        {
            float4 rz4 = *(const float4*)&rzp[n0 + kq * 4];
#pragma unroll
            for (int p = 0; p < 4; p++) {
                int c = c0 + p * 64;
                float4 vv = *(const float4*)&vp[(size_t)c * Nn + n0 + kq * 4];
                float* dst = &As[c][kq * 4];
                dst[0] = vv.x * rz4.x;
                dst[1] = vv.y * rz4.y;
                dst[2] = vv.z * rz4.z;
                dst[3] = vv.w * rz4.w;
            }
        }
        if (tid < Rr * BK) { int r = tid >> 4, kk = tid & 15; qs[r][kk] = qp[r * Nn + n0 + kk]; }
        if (tid < BK) mxs[tid] = mxp[n0 + tid];
        __syncthreads();
        // build E tile: thread = one m column, 8 kk rows
        {
            const int mm = tid & 127, kg = tid >> 7;
            float ktv[Rr];
#pragma unroll
            for (int r = 0; r < Rr; r++) ktv[r] = kt[r][mm];
#pragma unroll
            for (int jj = 0; jj < 8; jj++) {
                int kk = kg * 8 + jj;
                float s = 0.f;
#pragma unroll
                for (int r = 0; r < Rr; r++) s = fmaf(qs[r][kk], ktv[r], s);
                Es[kk][mm] = __expf(s - mxs[kk]);
            }
        }
        __syncthreads();
        // main FMA loop: 128 outputs/thread as 64 f32x2 accumulators
#pragma unroll
        for (int kk = 0; kk < BK; kk++) {
            unsigned long long ap[8];
#pragma unroll
            for (int jg = 0; jg < 4; jg++) {
                int c = ty * 4 + jg * 64;
                ap[jg * 2]     = pk2(As[c][kk],     As[c + 1][kk]);
                ap[jg * 2 + 1] = pk2(As[c + 2][kk], As[c + 3][kk]);
            }
            unsigned long long bs[8];
            float4 e0 = *(const float4*)&Es[kk][tx * 4];
            float4 e1 = *(const float4*)&Es[kk][64 + tx * 4];
            bs[0] = pk2(e0.x, e0.x); bs[1] = pk2(e0.y, e0.y);
            bs[2] = pk2(e0.z, e0.z); bs[3] = pk2(e0.w, e0.w);
            bs[4] = pk2(e1.x, e1.x); bs[5] = pk2(e1.y, e1.y);
            bs[6] = pk2(e1.z, e1.z); bs[7] = pk2(e1.w, e1.w);
#pragma unroll
            for (int i = 0; i < 8; i++)
#pragma unroll
                for (int j = 0; j < 8; j++)
                    acc[i][j] = ffma2(ap[i], bs[j], acc[i][j]);
        }
    }

    // epilogue: out = f + beta * O
    const float beta = *beta_p;
#pragma unroll
    for (int i = 0; i < 8; i++) {
        int c = ty * 4 + (i >> 1) * 64 + (i & 1) * 2;
#pragma unroll
        for (int row = 0; row < 2; row++) {
            int cc = c + row;
            const float* frow = f + (size_t)cc * Nn;
            float* orow = outp + (size_t)cc * Nn;
#pragma unroll
            for (int h = 0; h < 2; h++) {
                int col = m0 + h * 64 + tx * 4;
                float4 fv = *(const float4*)(frow + col);
                float r0 = row ? hi32(acc[i][h * 4 + 0]) : lo32(acc[i][h * 4 + 0]);
                float r1 = row ? hi32(acc[i][h * 4 + 1]) : lo32(acc[i][h * 4 + 1]);
                float r2 = row ? hi32(acc[i][h * 4 + 2]) : lo32(acc[i][h * 4 + 2]);
                float r3 = row ? hi32(acc[i][h * 4 + 3]) : lo32(acc[i][h * 4 + 3]);
                float4 ov;
                ov.x = fmaf(beta, r0, fv.x);
                ov.y = fmaf(beta, r1, fv.y);
                ov.z = fmaf(beta, r2, fv.z);
                ov.w = fmaf(beta, r3, fv.w);
                *(float4*)(orow + col) = ov;
            }
        }
    }
}

// ---------------- launch ------------------------------------------------------
extern "C" void kernel_launch(void* const* d_in, const int* in_sizes, int n_in,
                              void* d_out, int out_size) {
    (void)in_sizes; (void)n_in; (void)out_size;
    const float* fL   = (const float*)d_in[0];
    const float* fU   = (const float*)d_in[1];
    const float* qL_w = (const float*)d_in[2];
    const float* qL_b = (const float*)d_in[3];
    const float* kU_w = (const float*)d_in[4];
    const float* kU_b = (const float*)d_in[5];
    const float* vU_w = (const float*)d_in[6];
    const float* vU_b = (const float*)d_in[7];
    const float* qU_w = (const float*)d_in[8];
    const float* qU_b = (const float*)d_in[9];
    const float* kL_w = (const float*)d_in[10];
    const float* kL_b = (const float*)d_in[11];
    const float* vL_w = (const float*)d_in[12];
    const float* vL_b = (const float*)d_in[13];
    const float* beta = (const float*)d_in[14];
    float* out = (float*)d_out;

    proj2_kernel<<<dim3(Nn / 64, Bb), 64>>>(fL, qL_w, qL_b, kL_w, kL_b, 0);
    proj2_kernel<<<dim3(Nn / 64, Bb), 64>>>(fU, kU_w, kU_b, qU_w, qU_b, 1);
    gconv_kernel<<<dim3(Nn / 128, Gg, Bb * 2), 128>>>(fL, fU, vU_w, vU_b, vL_w, vL_b);
    stats_kernel<<<dim3(Nn / 256, 4, Bb * 2), 256>>>();
    combine_kernel<<<dim3(Nn / 256, Bb * 2), 256>>>();
    gemm_kernel<<<dim3(Nn / BN, Bb * 2), 256>>>(fL, fU, beta, out);
}

// round 2
// speedup vs baseline: 1.0009x; 1.0009x over previous
#include <cuda_runtime.h>
#include <cuda_bf16.h>

// Problem constants
#define Bb 2
#define Cc 256
#define Nn 4096
#define Rr 8
#define Gg 4

#define BM 256   // C tile (full)
#define BN 128   // m tile
#define BK 16    // n (contraction) tile

// ---------------- scratch (device globals; no allocation allowed) -------------
// indexed [dir][batch]
__device__ float g_q[2][Bb][Rr * Nn];
__device__ float g_k[2][Bb][Rr * Nn];
__device__ float g_v[2][Bb][Cc * Nn];
__device__ float g_mx[2][Bb][Nn];
__device__ float g_rz[2][Bb][Nn];
__device__ float g_pmx[2][Bb][4][Nn];
__device__ float g_psum[2][Bb][4][Nn];

// ---------------- f32x2 helpers (Blackwell packed fp32 FMA) -------------------
__device__ __forceinline__ unsigned long long pk2(float lo, float hi) {
    unsigned long long r;
    asm("mov.b64 %0, {%1, %2};" : "=l"(r) : "f"(lo), "f"(hi));
    return r;
}
__device__ __forceinline__ unsigned long long ffma2(unsigned long long a,
                                                    unsigned long long b,
                                                    unsigned long long c) {
    unsigned long long d;
    asm("fma.rn.f32x2 %0, %1, %2, %3;" : "=l"(d) : "l"(a), "l"(b), "l"(c));
    return d;
}
__device__ __forceinline__ float lo32(unsigned long long v) {
    return __uint_as_float((unsigned)(v & 0xffffffffull));
}
__device__ __forceinline__ float hi32(unsigned long long v) {
    return __uint_as_float((unsigned)(v >> 32));
}

// ---------------- projections: two R=8 1x1 convs per field -------------------
// field 0: x=fL -> outA=g_q[0] (w=qL), outB=g_k[1] (w=kL)
// field 1: x=fU -> outA=g_k[0] (w=kU), outB=g_q[1] (w=qU)
__global__ void proj2_kernel(const float* __restrict__ x,
                             const float* __restrict__ wA, const float* __restrict__ bA,
                             const float* __restrict__ wB, const float* __restrict__ bB,
                             int field) {
    __shared__ float ws[2 * Rr * Cc];
    const int tid = threadIdx.x;          // 64 threads
    const int b = blockIdx.y;
    const int n = blockIdx.x * 64 + tid;
    for (int i = tid; i < Rr * Cc; i += 64) {
        ws[i] = wA[i];
        ws[Rr * Cc + i] = wB[i];
    }
    __syncthreads();
    float acc[16];
#pragma unroll
    for (int r = 0; r < Rr; r++) { acc[r] = bA[r]; acc[8 + r] = bB[r]; }
    const float* xb = x + (size_t)b * Cc * Nn + n;
    for (int c = 0; c < Cc; c++) {
        float xv = xb[(size_t)c * Nn];
#pragma unroll
        for (int r = 0; r < Rr; r++) {
            acc[r]     = fmaf(ws[r * Cc + c], xv, acc[r]);
            acc[8 + r] = fmaf(ws[Rr * Cc + r * Cc + c], xv, acc[8 + r]);
        }
    }
    float* outA = (field == 0) ? g_q[0][b] : g_k[0][b];
    float* outB = (field == 0) ? g_k[1][b] : g_q[1][b];
#pragma unroll
    for (int r = 0; r < Rr; r++) {
        outA[r * Nn + n] = acc[r];
        outB[r * Nn + n] = acc[8 + r];
    }
}

// ---------------- grouped 1x1 conv (V projections) ----------------------------
// dir 0: v = vU(xU), dir 1: v = vL(xL)
__global__ void gconv_kernel(const float* __restrict__ fL, const float* __restrict__ fU,
                             const float* __restrict__ wU, const float* __restrict__ bU,
                             const float* __restrict__ wL, const float* __restrict__ bL) {
    const int bd = blockIdx.z;
    const int d = bd & 1;
    const int b = bd >> 1;
    const float* x    = (d == 0) ? fU : fL;
    const float* w    = (d == 0) ? wU : wL;
    const float* bias = (d == 0) ? bU : bL;
    const int g = blockIdx.y;
    const int tid = threadIdx.x;          // 128 threads
    const int n = blockIdx.x * 128 + tid;

    __shared__ float ws[64 * 64];
    for (int i = tid; i < 64 * 64; i += 128) ws[i] = w[g * 4096 + i];
    __syncthreads();

    float acc[64];
#pragma unroll
    for (int co = 0; co < 64; co++) acc[co] = bias[g * 64 + co];

    const float* xb = x + (size_t)b * Cc * Nn + (size_t)(g * 64) * Nn + n;
    for (int ci = 0; ci < 64; ci++) {
        float xv = xb[(size_t)ci * Nn];
#pragma unroll
        for (int co = 0; co < 64; co++)
            acc[co] = fmaf(ws[co * 64 + ci], xv, acc[co]);
    }
    float* vout = g_v[d][b];
#pragma unroll
    for (int co = 0; co < 64; co++)
        vout[(size_t)(g * 64 + co) * Nn + n] = acc[co];
}

// ---------------- softmax row stats: partial max + sumexp per m-chunk ---------
__global__ void stats_kernel() {
    const int bd = blockIdx.z;
    const int d = bd & 1;
    const int b = bd >> 1;
    const int mc = blockIdx.y;            // m chunk of 1024
    const int tid = threadIdx.x;          // 256 threads
    const int n = blockIdx.x * 256 + tid;

    __shared__ float ks[Rr][1024];        // 32 KB
    const float* kp = g_k[d][b];
    const float* qp = g_q[d][b];
    for (int i = tid; i < Rr * 1024; i += 256) {
        int r = i >> 10, mm = i & 1023;
        ks[r][mm] = kp[r * Nn + mc * 1024 + mm];
    }
    __syncthreads();

    float qr[Rr];
#pragma unroll
    for (int r = 0; r < Rr; r++) qr[r] = qp[r * Nn + n];

    float mxl = -3.0e38f;
    for (int m4 = 0; m4 < 256; m4++) {
        float s0 = 0.f, s1 = 0.f, s2 = 0.f, s3 = 0.f;
#pragma unroll
        for (int r = 0; r < Rr; r++) {
            float4 kv = *(const float4*)&ks[r][m4 * 4];
            s0 = fmaf(qr[r], kv.x, s0);
            s1 = fmaf(qr[r], kv.y, s1);
            s2 = fmaf(qr[r], kv.z, s2);
            s3 = fmaf(qr[r], kv.w, s3);
        }
        mxl = fmaxf(mxl, fmaxf(fmaxf(s0, s1), fmaxf(s2, s3)));
    }
    float sum = 0.f;
    for (int m4 = 0; m4 < 256; m4++) {
        float s0 = 0.f, s1 = 0.f, s2 = 0.f, s3 = 0.f;
#pragma unroll
        for (int r = 0; r < Rr; r++) {
            float4 kv = *(const float4*)&ks[r][m4 * 4];
            s0 = fmaf(qr[r], kv.x, s0);
            s1 = fmaf(qr[r], kv.y, s1);
            s2 = fmaf(qr[r], kv.z, s2);
            s3 = fmaf(qr[r], kv.w, s3);
        }
        sum += __expf(s0 - mxl) + __expf(s1 - mxl) + __expf(s2 - mxl) + __expf(s3 - mxl);
    }
    g_pmx[d][b][mc][n] = mxl;
    g_psum[d][b][mc][n] = sum;
}

__global__ void combine_kernel() {
    const int bd = blockIdx.y;
    const int d = bd & 1;
    const int b = bd >> 1;
    const int n = blockIdx.x * 256 + threadIdx.x;
    float m0 = g_pmx[d][b][0][n], m1 = g_pmx[d][b][1][n];
    float m2 = g_pmx[d][b][2][n], m3 = g_pmx[d][b][3][n];
    float gm = fmaxf(fmaxf(m0, m1), fmaxf(m2, m3));
    float Z = g_psum[d][b][0][n] * __expf(m0 - gm)
            + g_psum[d][b][1][n] * __expf(m1 - gm)
            + g_psum[d][b][2][n] * __expf(m2 - gm)
            + g_psum[d][b][3][n] * __expf(m3 - gm);
    g_mx[d][b][n] = gm;
    g_rz[d][b][n] = 1.0f / Z;
}

// ---------------- fused GEMM: out = f + beta * (V*rz) @ exp(Q^T K - mx) -------
__global__ void __launch_bounds__(256, 1)
gemm_kernel(const float* __restrict__ fL, const float* __restrict__ fU,
            const float* __restrict__ beta_p, float* __restrict__ outb) {
    const int bd = blockIdx.y;
    const int d = bd & 1;
    const int b = bd >> 1;
    const float* qp  = g_q[d][b];
    const float* kp  = g_k[d][b];
    const float* vp  = g_v[d][b];
    const float* mxp = g_mx[d][b];
    const float* rzp = g_rz[d][b];
    const float* f = ((d == 0) ? fL : fU) + (size_t)b * Cc * Nn;
    float* outp = outb + (size_t)d * Bb * Cc * Nn + (size_t)b * Cc * Nn;
    const int m0 = blockIdx.x * BN;

    __shared__ float As[Cc][20];          // V*rz tile, [c][kk], padded stride
    __shared__ float Es[BK][BN];          // exp tile
    __shared__ float kt[Rr][BN];          // k vectors for this m-tile
    __shared__ float qs[Rr][BK];
    __shared__ float mxs[BK];

    const int tid = threadIdx.x;
    const int tx = tid & 15, ty = tid >> 4;

    for (int i = tid; i < Rr * BN; i += 256) {
        int r = i >> 7, mm = i & 127;
        kt[r][mm] = kp[r * Nn + m0 + mm];
    }

    unsigned long long acc[8][8];
#pragma unroll
    for (int i = 0; i < 8; i++)
#pragma unroll
        for (int j = 0; j < 8; j++) acc[i][j] = 0ull;

    const int c0 = tid >> 2, kq = tid & 3;

    for (int n0 = 0; n0 < Nn; n0 += BK) {
        __syncthreads();
        // stage A tile (V * rz), transposing to [c][kk]
        {
            float4 rz4 = *(const float4*)&rzp[n0 + kq * 4];
#pragma unroll
            for (int p = 0; p < 4; p++) {
                int c = c0 + p * 64;
                float4 vv = *(const float4*)&vp[(size_t)c * Nn + n0 + kq * 4];
                float* dst = &As[c][kq * 4];
                dst[0] = vv.x * rz4.x;
                dst[1] = vv.y * rz4.y;
                dst[2] = vv.z * rz4.z;
                dst[3] = vv.w * rz4.w;
            }
        }
        if (tid < Rr * BK) { int r = tid >> 4, kk = tid & 15; qs[r][kk] = qp[r * Nn + n0 + kk]; }
        if (tid < BK) mxs[tid] = mxp[n0 + tid];
        __syncthreads();
        // build E tile: thread = one m column, 8 kk rows
        {
            const int mm = tid & 127, kg = tid >> 7;
            float ktv[Rr];
#pragma unroll
            for (int r = 0; r < Rr; r++) ktv[r] = kt[r][mm];
#pragma unroll
            for (int jj = 0; jj < 8; jj++) {
                int kk = kg * 8 + jj;
                float s = 0.f;
#pragma unroll
                for (int r = 0; r < Rr; r++) s = fmaf(qs[r][kk], ktv[r], s);
                Es[kk][mm] = __expf(s - mxs[kk]);
            }
        }
        __syncthreads();
        // main FMA loop: 128 outputs/thread as 64 f32x2 accumulators
#pragma unroll
        for (int kk = 0; kk < BK; kk++) {
            unsigned long long ap[8];
#pragma unroll
            for (int jg = 0; jg < 4; jg++) {
                int c = ty * 4 + jg * 64;
                ap[jg * 2]     = pk2(As[c][kk],     As[c + 1][kk]);
                ap[jg * 2 + 1] = pk2(As[c + 2][kk], As[c + 3][kk]);
            }
            unsigned long long bs[8];
            float4 e0 = *(const float4*)&Es[kk][tx * 4];
            float4 e1 = *(const float4*)&Es[kk][64 + tx * 4];
            bs[0] = pk2(e0.x, e0.x); bs[1] = pk2(e0.y, e0.y);
            bs[2] = pk2(e0.z, e0.z); bs[3] = pk2(e0.w, e0.w);
            bs[4] = pk2(e1.x, e1.x); bs[5] = pk2(e1.y, e1.y);
            bs[6] = pk2(e1.z, e1.z); bs[7] = pk2(e1.w, e1.w);
#pragma unroll
            for (int i = 0; i < 8; i++)
#pragma unroll
                for (int j = 0; j < 8; j++)
                    acc[i][j] = ffma2(ap[i], bs[j], acc[i][j]);
        }
    }

    // epilogue: out = f + beta * O
    const float beta = *beta_p;
#pragma unroll
    for (int i = 0; i < 8; i++) {
        int c = ty * 4 + (i >> 1) * 64 + (i & 1) * 2;
#pragma unroll
        for (int row = 0; row < 2; row++) {
            int cc = c + row;
            const float* frow = f + (size_t)cc * Nn;
            float* orow = outp + (size_t)cc * Nn;
#pragma unroll
            for (int h = 0; h < 2; h++) {
                int col = m0 + h * 64 + tx * 4;
                float4 fv = *(const float4*)(frow + col);
                float r0 = row ? hi32(acc[i][h * 4 + 0]) : lo32(acc[i][h * 4 + 0]);
                float r1 = row ? hi32(acc[i][h * 4 + 1]) : lo32(acc[i][h * 4 + 1]);
                float r2 = row ? hi32(acc[i][h * 4 + 2]) : lo32(acc[i][h * 4 + 2]);
                float r3 = row ? hi32(acc[i][h * 4 + 3]) : lo32(acc[i][h * 4 + 3]);
                float4 ov;
                ov.x = fmaf(beta, r0, fv.x);
                ov.y = fmaf(beta, r1, fv.y);
                ov.z = fmaf(beta, r2, fv.z);
                ov.w = fmaf(beta, r3, fv.w);
                *(float4*)(orow + col) = ov;
            }
        }
    }
}

// ---------------- launch ------------------------------------------------------
extern "C" void kernel_launch(void* const* d_in, const int* in_sizes, int n_in,
                              void* d_out, int out_size) {
    (void)in_sizes; (void)n_in; (void)out_size;
    const float* fL   = (const float*)d_in[0];
    const float* fU   = (const float*)d_in[1];
    const float* qL_w = (const float*)d_in[2];
    const float* qL_b = (const float*)d_in[3];
    const float* kU_w = (const float*)d_in[4];
    const float* kU_b = (const float*)d_in[5];
    const float* vU_w = (const float*)d_in[6];
    const float* vU_b = (const float*)d_in[7];
    const float* qU_w = (const float*)d_in[8];
    const float* qU_b = (const float*)d_in[9];
    const float* kL_w = (const float*)d_in[10];
    const float* kL_b = (const float*)d_in[11];
    const float* vL_w = (const float*)d_in[12];
    const float* vL_b = (const float*)d_in[13];
    const float* beta = (const float*)d_in[14];
    float* out = (float*)d_out;

    proj2_kernel<<<dim3(Nn / 64, Bb), 64>>>(fL, qL_w, qL_b, kL_w, kL_b, 0);
    proj2_kernel<<<dim3(Nn / 64, Bb), 64>>>(fU, kU_w, kU_b, qU_w, qU_b, 1);
    gconv_kernel<<<dim3(Nn / 128, Gg, Bb * 2), 128>>>(fL, fU, vU_w, vU_b, vL_w, vL_b);
    stats_kernel<<<dim3(Nn / 256, 4, Bb * 2), 256>>>();
    combine_kernel<<<dim3(Nn / 256, Bb * 2), 256>>>();
    gemm_kernel<<<dim3(Nn / BN, Bb * 2), 256>>>(fL, fU, beta, out);
}

// round 3
// speedup vs baseline: 1.0013x; 1.0003x over previous
#include <cuda_runtime.h>
#include <cuda_bf16.h>

// Problem constants
#define Bb 2
#define Cc 256
#define Nn 4096
#define Rr 8
#define Gg 4

#define BM 256   // C tile (full)
#define BN 128   // m tile
#define BK 16    // n (contraction) tile

// ---------------- scratch (device globals; no allocation allowed) -------------
// indexed [dir][batch]
__device__ float g_q[2][Bb][Rr * Nn];
__device__ float g_k[2][Bb][Rr * Nn];
__device__ float g_v[2][Bb][Cc * Nn];
__device__ float g_mx[2][Bb][Nn];
__device__ float g_rz[2][Bb][Nn];
__device__ float g_pmx[2][Bb][4][Nn];
__device__ float g_psum[2][Bb][4][Nn];

// ---------------- f32x2 helpers (Blackwell packed fp32 FMA) -------------------
__device__ __forceinline__ unsigned long long pk2(float lo, float hi) {
    unsigned long long r;
    asm("mov.b64 %0, {%1, %2};" : "=l"(r) : "f"(lo), "f"(hi));
    return r;
}
__device__ __forceinline__ unsigned long long ffma2(unsigned long long a,
                                                    unsigned long long b,
                                                    unsigned long long c) {
    unsigned long long d;
    asm("fma.rn.f32x2 %0, %1, %2, %3;" : "=l"(d) : "l"(a), "l"(b), "l"(c));
    return d;
}
__device__ __forceinline__ float lo32(unsigned long long v) {
    return __uint_as_float((unsigned)(v & 0xffffffffull));
}
__device__ __forceinline__ float hi32(unsigned long long v) {
    return __uint_as_float((unsigned)(v >> 32));
}

// ---------------- projections: two R=8 1x1 convs per field -------------------
// field 0: x=fL -> outA=g_q[0] (w=qL), outB=g_k[1] (w=kL)
// field 1: x=fU -> outA=g_k[0] (w=kU), outB=g_q[1] (w=qU)
__global__ void proj2_kernel(const float* __restrict__ x,
                             const float* __restrict__ wA, const float* __restrict__ bA,
                             const float* __restrict__ wB, const float* __restrict__ bB,
                             int field) {
    __shared__ float ws[2 * Rr * Cc];
    const int tid = threadIdx.x;          // 64 threads
    const int b = blockIdx.y;
    const int n = blockIdx.x * 64 + tid;
    for (int i = tid; i < Rr * Cc; i += 64) {
        ws[i] = wA[i];
        ws[Rr * Cc + i] = wB[i];
    }
    __syncthreads();
    float acc[16];
#pragma unroll
    for (int r = 0; r < Rr; r++) { acc[r] = bA[r]; acc[8 + r] = bB[r]; }
    const float* xb = x + (size_t)b * Cc * Nn + n;
    for (int c = 0; c < Cc; c++) {
        float xv = xb[(size_t)c * Nn];
#pragma unroll
        for (int r = 0; r < Rr; r++) {
            acc[r]     = fmaf(ws[r * Cc + c], xv, acc[r]);
            acc[8 + r] = fmaf(ws[Rr * Cc + r * Cc + c], xv, acc[8 + r]);
        }
    }
    float* outA = (field == 0) ? g_q[0][b] : g_k[0][b];
    float* outB = (field == 0) ? g_k[1][b] : g_q[1][b];
#pragma unroll
    for (int r = 0; r < Rr; r++) {
        outA[r * Nn + n] = acc[r];
        outB[r * Nn + n] = acc[8 + r];
    }
}

// ---------------- grouped 1x1 conv (V projections) ----------------------------
// dir 0: v = vU(xU), dir 1: v = vL(xL)
__global__ void gconv_kernel(const float* __restrict__ fL, const float* __restrict__ fU,
                             const float* __restrict__ wU, const float* __restrict__ bU,
                             const float* __restrict__ wL, const float* __restrict__ bL) {
    const int bd = blockIdx.z;
    const int d = bd & 1;
    const int b = bd >> 1;
    const float* x    = (d == 0) ? fU : fL;
    const float* w    = (d == 0) ? wU : wL;
    const float* bias = (d == 0) ? bU : bL;
    const int g = blockIdx.y;
    const int tid = threadIdx.x;          // 128 threads
    const int n = blockIdx.x * 128 + tid;

    __shared__ float ws[64 * 64];
    for (int i = tid; i < 64 * 64; i += 128) ws[i] = w[g * 4096 + i];
    __syncthreads();

    float acc[64];
#pragma unroll
    for (int co = 0; co < 64; co++) acc[co] = bias[g * 64 + co];

    const float* xb = x + (size_t)b * Cc * Nn + (size_t)(g * 64) * Nn + n;
    for (int ci = 0; ci < 64; ci++) {
        float xv = xb[(size_t)ci * Nn];
#pragma unroll
        for (int co = 0; co < 64; co++)
            acc[co] = fmaf(ws[co * 64 + ci], xv, acc[co]);
    }
    float* vout = g_v[d][b];
#pragma unroll
    for (int co = 0; co < 64; co++)
        vout[(size_t)(g * 64 + co) * Nn + n] = acc[co];
}

// ---------------- softmax row stats: partial max + sumexp per m-chunk ---------
__global__ void stats_kernel() {
    const int bd = blockIdx.z;
    const int d = bd & 1;
    const int b = bd >> 1;
    const int mc = blockIdx.y;            // m chunk of 1024
    const int tid = threadIdx.x;          // 256 threads
    const int n = blockIdx.x * 256 + tid;

    __shared__ float ks[Rr][1024];        // 32 KB
    const float* kp = g_k[d][b];
    const float* qp = g_q[d][b];
    for (int i = tid; i < Rr * 1024; i += 256) {
        int r = i >> 10, mm = i & 1023;
        ks[r][mm] = kp[r * Nn + mc * 1024 + mm];
    }
    __syncthreads();

    float qr[Rr];
#pragma unroll
    for (int r = 0; r < Rr; r++) qr[r] = qp[r * Nn + n];

    float mxl = -3.0e38f;
    for (int m4 = 0; m4 < 256; m4++) {
        float s0 = 0.f, s1 = 0.f, s2 = 0.f, s3 = 0.f;
#pragma unroll
        for (int r = 0; r < Rr; r++) {
            float4 kv = *(const float4*)&ks[r][m4 * 4];
            s0 = fmaf(qr[r], kv.x, s0);
            s1 = fmaf(qr[r], kv.y, s1);
            s2 = fmaf(qr[r], kv.z, s2);
            s3 = fmaf(qr[r], kv.w, s3);
        }
        mxl = fmaxf(mxl, fmaxf(fmaxf(s0, s1), fmaxf(s2, s3)));
    }
    float sum = 0.f;
    for (int m4 = 0; m4 < 256; m4++) {
        float s0 = 0.f, s1 = 0.f, s2 = 0.f, s3 = 0.f;
#pragma unroll
        for (int r = 0; r < Rr; r++) {
            float4 kv = *(const float4*)&ks[r][m4 * 4];
            s0 = fmaf(qr[r], kv.x, s0);
            s1 = fmaf(qr[r], kv.y, s1);
            s2 = fmaf(qr[r], kv.z, s2);
            s3 = fmaf(qr[r], kv.w, s3);
        }
        sum += __expf(s0 - mxl) + __expf(s1 - mxl) + __expf(s2 - mxl) + __expf(s3 - mxl);
    }
    g_pmx[d][b][mc][n] = mxl;
    g_psum[d][b][mc][n] = sum;
}

__global__ void combine_kernel() {
    const int bd = blockIdx.y;
    const int d = bd & 1;
    const int b = bd >> 1;
    const int n = blockIdx.x * 256 + threadIdx.x;
    float m0 = g_pmx[d][b][0][n], m1 = g_pmx[d][b][1][n];
    float m2 = g_pmx[d][b][2][n], m3 = g_pmx[d][b][3][n];
    float gm = fmaxf(fmaxf(m0, m1), fmaxf(m2, m3));
    float Z = g_psum[d][b][0][n] * __expf(m0 - gm)
            + g_psum[d][b][1][n] * __expf(m1 - gm)
            + g_psum[d][b][2][n] * __expf(m2 - gm)
            + g_psum[d][b][3][n] * __expf(m3 - gm);
    g_mx[d][b][n] = gm;
    g_rz[d][b][n] = 1.0f / Z;
}

// ---------------- fused GEMM: out = f + beta * (V*rz) @ exp(Q^T K - mx) -------
__global__ void __launch_bounds__(256, 1)
gemm_kernel(const float* __restrict__ fL, const float* __restrict__ fU,
            const float* __restrict__ beta_p, float* __restrict__ outb) {
    const int bd = blockIdx.y;
    const int d = bd & 1;
    const int b = bd >> 1;
    const float* qp  = g_q[d][b];
    const float* kp  = g_k[d][b];
    const float* vp  = g_v[d][b];
    const float* mxp = g_mx[d][b];
    const float* rzp = g_rz[d][b];
    const float* f = ((d == 0) ? fL : fU) + (size_t)b * Cc * Nn;
    float* outp = outb + (size_t)d * Bb * Cc * Nn + (size_t)b * Cc * Nn;
    const int m0 = blockIdx.x * BN;

    __shared__ float As[Cc][20];          // V*rz tile, [c][kk], padded stride
    __shared__ float Es[BK][BN];          // exp tile
    __shared__ float kt[Rr][BN];          // k vectors for this m-tile
    __shared__ float qs[Rr][BK];
    __shared__ float mxs[BK];

    const int tid = threadIdx.x;
    const int tx = tid & 15, ty = tid >> 4;

    for (int i = tid; i < Rr * BN; i += 256) {
        int r = i >> 7, mm = i & 127;
        kt[r][mm] = kp[r * Nn + m0 + mm];
    }

    unsigned long long acc[8][8];
#pragma unroll
    for (int i = 0; i < 8; i++)
#pragma unroll
        for (int j = 0; j < 8; j++) acc[i][j] = 0ull;

    const int c0 = tid >> 2, kq = tid & 3;

    for (int n0 = 0; n0 < Nn; n0 += BK) {
        __syncthreads();
        // stage A tile (V * rz), transposing to [c][kk]
        {
            float4 rz4 = *(const float4*)&rzp[n0 + kq * 4];
#pragma unroll
            for (int p = 0; p < 4; p++) {
                int c = c0 + p * 64;
                float4 vv = *(const float4*)&vp[(size_t)c * Nn + n0 + kq * 4];
                float* dst = &As[c][kq * 4];
                dst[0] = vv.x * rz4.x;
                dst[1] = vv.y * rz4.y;
                dst[2] = vv.z * rz4.z;
                dst[3] = vv.w * rz4.w;
            }
        }
        if (tid < Rr * BK) { int r = tid >> 4, kk = tid & 15; qs[r][kk] = qp[r * Nn + n0 + kk]; }
        if (tid < BK) mxs[tid] = mxp[n0 + tid];
        __syncthreads();
        // build E tile: thread = one m column, 8 kk rows
        {
            const int mm = tid & 127, kg = tid >> 7;
            float ktv[Rr];
#pragma unroll
            for (int r = 0; r < Rr; r++) ktv[r] = kt[r][mm];
#pragma unroll
            for (int jj = 0; jj < 8; jj++) {
                int kk = kg * 8 + jj;
                float s = 0.f;
#pragma unroll
                for (int r = 0; r < Rr; r++) s = fmaf(qs[r][kk], ktv[r], s);
                Es[kk][mm] = __expf(s - mxs[kk]);
            }
        }
        __syncthreads();
        // main FMA loop: 128 outputs/thread as 64 f32x2 accumulators
#pragma unroll
        for (int kk = 0; kk < BK; kk++) {
            unsigned long long ap[8];
#pragma unroll
            for (int jg = 0; jg < 4; jg++) {
                int c = ty * 4 + jg * 64;
                ap[jg * 2]     = pk2(As[c][kk],     As[c + 1][kk]);
                ap[jg * 2 + 1] = pk2(As[c + 2][kk], As[c + 3][kk]);
            }
            unsigned long long bs[8];
            float4 e0 = *(const float4*)&Es[kk][tx * 4];
            float4 e1 = *(const float4*)&Es[kk][64 + tx * 4];
            bs[0] = pk2(e0.x, e0.x); bs[1] = pk2(e0.y, e0.y);
            bs[2] = pk2(e0.z, e0.z); bs[3] = pk2(e0.w, e0.w);
            bs[4] = pk2(e1.x, e1.x); bs[5] = pk2(e1.y, e1.y);
            bs[6] = pk2(e1.z, e1.z); bs[7] = pk2(e1.w, e1.w);
#pragma unroll
            for (int i = 0; i < 8; i++)
#pragma unroll
                for (int j = 0; j < 8; j++)
                    acc[i][j] = ffma2(ap[i], bs[j], acc[i][j]);
        }
    }

    // epilogue: out = f + beta * O
    const float beta = *beta_p;
#pragma unroll
    for (int i = 0; i < 8; i++) {
        int c = ty * 4 + (i >> 1) * 64 + (i & 1) * 2;
#pragma unroll
        for (int row = 0; row < 2; row++) {
            int cc = c + row;
            const float* frow = f + (size_t)cc * Nn;
            float* orow = outp + (size_t)cc * Nn;
#pragma unroll
            for (int h = 0; h < 2; h++) {
                int col = m0 + h * 64 + tx * 4;
                float4 fv = *(const float4*)(frow + col);
                float r0 = row ? hi32(acc[i][h * 4 + 0]) : lo32(acc[i][h * 4 + 0]);
                float r1 = row ? hi32(acc[i][h * 4 + 1]) : lo32(acc[i][h * 4 + 1]);
                float r2 = row ? hi32(acc[i][h * 4 + 2]) : lo32(acc[i][h * 4 + 2]);
                float r3 = row ? hi32(acc[i][h * 4 + 3]) : lo32(acc[i][h * 4 + 3]);
                float4 ov;
                ov.x = fmaf(beta, r0, fv.x);
                ov.y = fmaf(beta, r1, fv.y);
                ov.z = fmaf(beta, r2, fv.z);
                ov.w = fmaf(beta, r3, fv.w);
                *(float4*)(orow + col) = ov;
            }
        }
    }
}

// ---------------- launch ------------------------------------------------------
extern "C" void kernel_launch(void* const* d_in, const int* in_sizes, int n_in,
                              void* d_out, int out_size) {
    (void)in_sizes; (void)n_in; (void)out_size;
    const float* fL   = (const float*)d_in[0];
    const float* fU   = (const float*)d_in[1];
    const float* qL_w = (const float*)d_in[2];
    const float* qL_b = (const float*)d_in[3];
    const float* kU_w = (const float*)d_in[4];
    const float* kU_b = (const float*)d_in[5];
    const float* vU_w = (const float*)d_in[6];
    const float* vU_b = (const float*)d_in[7];
    const float* qU_w = (const float*)d_in[8];
    const float* qU_b = (const float*)d_in[9];
    const float* kL_w = (const float*)d_in[10];
    const float* kL_b = (const float*)d_in[11];
    const float* vL_w = (const float*)d_in[12];
    const float* vL_b = (const float*)d_in[13];
    const float* beta = (const float*)d_in[14];
    float* out = (float*)d_out;

    proj2_kernel<<<dim3(Nn / 64, Bb), 64>>>(fL, qL_w, qL_b, kL_w, kL_b, 0);
    proj2_kernel<<<dim3(Nn / 64, Bb), 64>>>(fU, kU_w, kU_b, qU_w, qU_b, 1);
    gconv_kernel<<<dim3(Nn / 128, Gg, Bb * 2), 128>>>(fL, fU, vU_w, vU_b, vL_w, vL_b);
    stats_kernel<<<dim3(Nn / 256, 4, Bb * 2), 256>>>();
    combine_kernel<<<dim3(Nn / 256, Bb * 2), 256>>>();
    gemm_kernel<<<dim3(Nn / BN, Bb * 2), 256>>>(fL, fU, beta, out);
}